// round 8
// baseline (speedup 1.0000x reference)
#include <cuda_runtime.h>
#include <stdint.h>
#include <math.h>

// Problem constants (fixed shapes for this problem)
#define MAXN 20000
#define MAXE 320000
#define SED  768
#define HC1  512      // 4 heads * 128
#define C1   128
#define H1   4
#define C2   128

// ---------------- scratch (no allocation allowed; bss device globals) ----------------
__device__ __align__(16) float g_h1[MAXN * HC1];     // layer1 pre-attention features
__device__ __align__(16) float g_act1[MAXN * HC1];   // layer1 output after elu
__device__ __align__(16) float g_h3[MAXN * C2];      // layer2 pre-attention features
__device__ __align__(16) float g_esrc1[MAXN * 4];
__device__ __align__(16) float g_edst1[MAXN * 4];
__device__ float g_esrc2[MAXN];
__device__ float g_edst2[MAXN];
__device__ __align__(16) float g_c1[HC1];            // sent @ W1[768:] constant vector
__device__ int g_cnt[MAXN];
__device__ int g_rowptr[MAXN + 1];
__device__ int g_cursor[MAXN];
__device__ int g_col[MAXE];
__device__ int g_bsum[64];
__device__ int g_boff[64];

__device__ __forceinline__ float lrelu(float x) { return x > 0.f ? x : 0.2f * x; }

__device__ __forceinline__ void cp16(unsigned saddr, const void* gaddr, bool ok) {
    int sz = ok ? 16 : 0;
    asm volatile("cp.async.cg.shared.global [%0], [%1], 16, %2;"
                 :: "r"(saddr), "l"(gaddr), "r"(sz) : "memory");
}
__device__ __forceinline__ void cp_commit() {
    asm volatile("cp.async.commit_group;" ::: "memory");
}
__device__ __forceinline__ void cp_wait2() {
    asm volatile("cp.async.wait_group 2;" ::: "memory");
}

// ---------------- CSR build ----------------
__global__ void k_count(const int* __restrict__ ei, int E) {
    int i = blockIdx.x * blockDim.x + threadIdx.x;
    if (i < E) atomicAdd(&g_cnt[ei[E + i]], 1);
}

__global__ void k_scan1(int N) {
    __shared__ int sm[512];
    int b = blockIdx.x, t = threadIdx.x, i = b * 512 + t;
    int v = (i < N) ? g_cnt[i] : 0;
    sm[t] = v;
    __syncthreads();
#pragma unroll
    for (int off = 1; off < 512; off <<= 1) {
        int u = (t >= off) ? sm[t - off] : 0;
        __syncthreads();
        sm[t] += u;
        __syncthreads();
    }
    if (i < N) g_rowptr[i + 1] = sm[t];
    if (t == 511) g_bsum[b] = sm[511];
}

__global__ void k_scan2(int nb) {
    __shared__ int sm[64];
    int t = threadIdx.x;
    int v = (t < nb) ? g_bsum[t] : 0;
    sm[t] = v;
    __syncthreads();
#pragma unroll
    for (int off = 1; off < 64; off <<= 1) {
        int u = (t >= off) ? sm[t - off] : 0;
        __syncthreads();
        sm[t] += u;
        __syncthreads();
    }
    if (t < nb) g_boff[t] = sm[t] - v;
}

__global__ void k_scan3(int N) {
    int i = blockIdx.x * blockDim.x + threadIdx.x;
    if (i < N) {
        int r = g_rowptr[i + 1] + g_boff[i >> 9];
        g_rowptr[i + 1] = r;
        g_cursor[i] = r - g_cnt[i];
    }
    if (i == 0) g_rowptr[0] = 0;
}

__global__ void k_scatter(const int* __restrict__ ei, int E) {
    int i = blockIdx.x * blockDim.x + threadIdx.x;
    if (i < E) {
        int dst = ei[E + i], src = ei[i];
        int pos = atomicAdd(&g_cursor[dst], 1);
        g_col[pos] = src;
    }
}

// ---------------- constant vector: c1 = sent @ W1[768:1536, :] ----------------
__global__ void k_constvec(const float* __restrict__ sent, const float* __restrict__ W1) {
    int j = blockIdx.x * blockDim.x + threadIdx.x;
    if (j < HC1) {
        float s = 0.f;
        for (int k = 0; k < SED; k++)
            s += sent[k] * W1[(size_t)(SED + k) * HC1 + j];
        g_c1[j] = s;
    }
}

// ---------------- TF32 tensor-core GEMM, cp.async 4-stage, fused e-dot epilogue ----------------
// C[M,N] = A[M,K] @ B[K,N] (+ addv[col]); also per-row dots with a_src/a_dst over this
// CTA's 128-col block (one head) -> es_out[row*es_stride + blockIdx.y], ed_out likewise.
// Raw fp32 bits fed to tf32 mma (HW truncates low mantissa bits).
// N % 128 == 0, K % 16 == 0; M bounds-checked.
#define LDA 24
#define LDB 132
#define A_STG (128 * LDA)          // 3072 floats per stage
#define B_STG (16 * LDB)           // 2112 floats per stage
#define B_BASE (4 * A_STG)         // 12288 floats
#define GSMEM_FLOATS (B_BASE + 4 * B_STG)   // 20736 floats = 82944 B

__global__ __launch_bounds__(256, 2)
void k_gemm_tf32(const float* __restrict__ A, const float* __restrict__ B,
                 float* __restrict__ C, const float* __restrict__ addv,
                 const float* __restrict__ asrc, const float* __restrict__ adst,
                 float* __restrict__ es_out, float* __restrict__ ed_out,
                 int es_stride, int M, int N, int K) {
    extern __shared__ float smem[];

    int tid = threadIdx.x;
    int lane = tid & 31, wid = tid >> 5;
    int g = lane >> 2, t = lane & 3;
    int wm = (wid >> 2) * 64, wn = (wid & 3) * 32;
    int m0 = blockIdx.x * 128, n0 = blockIdx.y * 128;

    // cp.async chunk assignment: A 512 chunks (row=c>>2, k=(c&3)*4), B 512 chunks
    int ac0 = tid, ac1 = tid + 256;
    int a_r0 = ac0 >> 2, a_k0 = (ac0 & 3) * 4;
    int a_r1 = ac1 >> 2, a_k1 = (ac1 & 3) * 4;
    bool a_ok0 = (m0 + a_r0) < M, a_ok1 = (m0 + a_r1) < M;
    const float* Ag0 = A + (size_t)(m0 + a_r0) * K + a_k0;
    const float* Ag1 = A + (size_t)(m0 + a_r1) * K + a_k1;
    int b_r0 = tid >> 5, b_n0c = (tid & 31) * 4;          // chunks 0..255
    int b_r1 = b_r0 + 8;                                   // chunks 256..511
    const float* Bg0 = B + (size_t)b_r0 * N + n0 + b_n0c;
    const float* Bg1 = B + (size_t)b_r1 * N + n0 + b_n0c;

    unsigned smb = (unsigned)__cvta_generic_to_shared(smem);
    unsigned sa0 = smb + (unsigned)(a_r0 * LDA + a_k0) * 4u;
    unsigned sa1 = smb + (unsigned)(a_r1 * LDA + a_k1) * 4u;
    unsigned sb0 = smb + (unsigned)(B_BASE + b_r0 * LDB + b_n0c) * 4u;
    unsigned sb1 = smb + (unsigned)(B_BASE + b_r1 * LDB + b_n0c) * 4u;

    float acc[4][4][4];
#pragma unroll
    for (int mi = 0; mi < 4; mi++)
#pragma unroll
        for (int ni = 0; ni < 4; ni++)
#pragma unroll
            for (int c = 0; c < 4; c++) acc[mi][ni][c] = 0.f;

    int nk = K / 16;

    // prologue: issue 3 stages
#pragma unroll
    for (int s = 0; s < 3; s++) {
        if (s < nk) {
            size_t ko = (size_t)s * 16;
            cp16(sa0 + (unsigned)s * A_STG * 4u, Ag0 + ko, a_ok0);
            cp16(sa1 + (unsigned)s * A_STG * 4u, Ag1 + ko, a_ok1);
            cp16(sb0 + (unsigned)s * B_STG * 4u, Bg0 + ko * N, true);
            cp16(sb1 + (unsigned)s * B_STG * 4u, Bg1 + ko * N, true);
        }
        cp_commit();
    }
    cp_wait2();
    __syncthreads();

    for (int kt = 0; kt < nk; kt++) {
        int buf = kt & 3;
        const float* as = smem + buf * A_STG;
        const float* bs = smem + B_BASE + buf * B_STG;
#pragma unroll
        for (int ks = 0; ks < 2; ks++) {
            int kb = ks * 8;
            float2 af[4][2];
#pragma unroll
            for (int mi = 0; mi < 4; mi++) {
                int r = wm + mi * 16 + g;
                af[mi][0] = *(const float2*)&as[r * LDA + kb + 2 * t];
                af[mi][1] = *(const float2*)&as[(r + 8) * LDA + kb + 2 * t];
            }
#pragma unroll
            for (int ni = 0; ni < 4; ni++) {
                int cidx = wn + ni * 8 + g;
                unsigned b0 = __float_as_uint(bs[(kb + 2 * t) * LDB + cidx]);
                unsigned b1 = __float_as_uint(bs[(kb + 2 * t + 1) * LDB + cidx]);
#pragma unroll
                for (int mi = 0; mi < 4; mi++) {
                    unsigned a0 = __float_as_uint(af[mi][0].x);
                    unsigned a1 = __float_as_uint(af[mi][1].x);
                    unsigned a2 = __float_as_uint(af[mi][0].y);
                    unsigned a3 = __float_as_uint(af[mi][1].y);
                    asm volatile(
                        "mma.sync.aligned.m16n8k8.row.col.f32.tf32.tf32.f32 "
                        "{%0,%1,%2,%3}, {%4,%5,%6,%7}, {%8,%9}, {%0,%1,%2,%3};"
                        : "+f"(acc[mi][ni][0]), "+f"(acc[mi][ni][1]),
                          "+f"(acc[mi][ni][2]), "+f"(acc[mi][ni][3])
                        : "r"(a0), "r"(a1), "r"(a2), "r"(a3), "r"(b0), "r"(b1));
                }
            }
        }
        int nxt = kt + 3;
        if (nxt < nk) {
            unsigned nbuf = (unsigned)(nxt & 3);
            size_t ko = (size_t)nxt * 16;
            cp16(sa0 + nbuf * A_STG * 4u, Ag0 + ko, a_ok0);
            cp16(sa1 + nbuf * A_STG * 4u, Ag1 + ko, a_ok1);
            cp16(sb0 + nbuf * B_STG * 4u, Bg0 + ko * N, true);
            cp16(sb1 + nbuf * B_STG * 4u, Bg1 + ko * N, true);
        }
        cp_commit();
        cp_wait2();
        __syncthreads();
    }

    // attention vectors for this CTA's cols
    float a_s[8], a_d[8];
#pragma unroll
    for (int ni = 0; ni < 4; ni++)
#pragma unroll
        for (int j = 0; j < 2; j++) {
            int c = n0 + wn + ni * 8 + 2 * t + j;
            a_s[ni * 2 + j] = asrc[c];
            a_d[ni * 2 + j] = adst[c];
        }

    // epilogue: store C (+addv), accumulate per-row dots
    float* sds = smem;                 // [128][4]
    float* sdd = smem + 512;           // [128][4]
#pragma unroll
    for (int mi = 0; mi < 4; mi++) {
#pragma unroll
        for (int half = 0; half < 2; half++) {
            int rl = wm + mi * 16 + g + half * 8;
            int r = m0 + rl;
            float ps = 0.f, pd = 0.f;
#pragma unroll
            for (int ni = 0; ni < 4; ni++) {
                int c = n0 + wn + ni * 8 + 2 * t;
                float2 v;
                v.x = acc[mi][ni][half * 2 + 0];
                v.y = acc[mi][ni][half * 2 + 1];
                if (addv) { v.x += addv[c]; v.y += addv[c + 1]; }
                if (r < M) *(float2*)&C[(size_t)r * N + c] = v;
                ps = fmaf(v.x, a_s[ni * 2], ps);
                ps = fmaf(v.y, a_s[ni * 2 + 1], ps);
                pd = fmaf(v.x, a_d[ni * 2], pd);
                pd = fmaf(v.y, a_d[ni * 2 + 1], pd);
            }
            // reduce across the 4 t-lanes sharing this row
            ps += __shfl_xor_sync(0xffffffffu, ps, 1);
            ps += __shfl_xor_sync(0xffffffffu, ps, 2);
            pd += __shfl_xor_sync(0xffffffffu, pd, 1);
            pd += __shfl_xor_sync(0xffffffffu, pd, 2);
            if (t == 0) { sds[rl * 4 + (wid & 3)] = ps; sdd[rl * 4 + (wid & 3)] = pd; }
        }
    }
    __syncthreads();
    if (tid < 128) {
        int r = m0 + tid;
        if (r < M) {
            float s = sds[tid * 4] + sds[tid * 4 + 1] + sds[tid * 4 + 2] + sds[tid * 4 + 3];
            float d = sdd[tid * 4] + sdd[tid * 4 + 1] + sdd[tid * 4 + 2] + sdd[tid * 4 + 3];
            es_out[(size_t)r * es_stride + blockIdx.y] = s;
            ed_out[(size_t)r * es_stride + blockIdx.y] = d;
        }
    }
}

// ---------------- layer 1 aggregation: single-sweep normalization ----------------
__global__ void k_agg1(const float* __restrict__ b1) {
    int n = blockIdx.x;
    int t = threadIdx.x, lane = t & 31, w = t >> 5;
    int start = g_rowptr[n], end = g_rowptr[n + 1];
    float4 edv = *(const float4*)&g_edst1[n * 4];

    __shared__ float4 wbuf[128];
    __shared__ int scol[128];
    __shared__ float sred[4][4];

    float acc[4] = {0.f, 0.f, 0.f, 0.f};
    float ss[4]  = {0.f, 0.f, 0.f, 0.f};

    for (int base = start; base < end; base += 128) {
        int i = base + t;
        if (i < end) {
            int sc = g_col[i];
            float4 es = *(const float4*)&g_esrc1[sc * 4];
            float4 wv;
            wv.x = __expf(lrelu(es.x + edv.x));
            wv.y = __expf(lrelu(es.y + edv.y));
            wv.z = __expf(lrelu(es.z + edv.z));
            wv.w = __expf(lrelu(es.w + edv.w));
            ss[0] += wv.x; ss[1] += wv.y; ss[2] += wv.z; ss[3] += wv.w;
            wbuf[t] = wv;
            scol[t] = sc;
        }
        __syncthreads();
        int cnt = min(128, end - base);
        int j = 0;
        for (; j + 1 < cnt; j += 2) {
            int s0 = scol[j], s1 = scol[j + 1];
            float4 w0 = wbuf[j], w1 = wbuf[j + 1];
            const float* p0 = &g_h1[(size_t)s0 * HC1];
            const float* p1 = &g_h1[(size_t)s1 * HC1];
            float v00 = p0[t], v01 = p0[128 + t], v02 = p0[256 + t], v03 = p0[384 + t];
            float v10 = p1[t], v11 = p1[128 + t], v12 = p1[256 + t], v13 = p1[384 + t];
            acc[0] = fmaf(w0.x, v00, acc[0]);
            acc[1] = fmaf(w0.y, v01, acc[1]);
            acc[2] = fmaf(w0.z, v02, acc[2]);
            acc[3] = fmaf(w0.w, v03, acc[3]);
            acc[0] = fmaf(w1.x, v10, acc[0]);
            acc[1] = fmaf(w1.y, v11, acc[1]);
            acc[2] = fmaf(w1.z, v12, acc[2]);
            acc[3] = fmaf(w1.w, v13, acc[3]);
        }
        if (j < cnt) {
            int s0 = scol[j];
            float4 w0 = wbuf[j];
            const float* p0 = &g_h1[(size_t)s0 * HC1];
            acc[0] = fmaf(w0.x, p0[t],       acc[0]);
            acc[1] = fmaf(w0.y, p0[128 + t], acc[1]);
            acc[2] = fmaf(w0.z, p0[256 + t], acc[2]);
            acc[3] = fmaf(w0.w, p0[384 + t], acc[3]);
        }
        __syncthreads();
    }

#pragma unroll
    for (int h = 0; h < 4; h++)
#pragma unroll
        for (int off = 16; off; off >>= 1)
            ss[h] += __shfl_xor_sync(0xffffffffu, ss[h], off);
    if (lane == 0) { sred[0][w] = ss[0]; sred[1][w] = ss[1]; sred[2][w] = ss[2]; sred[3][w] = ss[3]; }
    __syncthreads();

    float* orow = &g_act1[(size_t)n * HC1];
#pragma unroll
    for (int h = 0; h < 4; h++) {
        float s = sred[h][0] + sred[h][1] + sred[h][2] + sred[h][3];
        float inv = (s > 0.f) ? 1.f / s : 0.f;   // deg-0 node -> out = bias
        float v = acc[h] * inv + b1[h * C1 + t];
        orow[h * C1 + t] = v > 0.f ? v : expm1f(v);
    }
}

// ---------------- layer 2 aggregation -> final output ----------------
__global__ void k_agg2(const float* __restrict__ b2, float* __restrict__ out) {
    int n = blockIdx.x;
    int t = threadIdx.x, lane = t & 31, w = t >> 5;
    int start = g_rowptr[n], end = g_rowptr[n + 1];
    float ed = g_edst2[n];

    __shared__ float wbuf[128];
    __shared__ int scol[128];
    __shared__ float sred[4];

    float acc = 0.f, ss = 0.f;

    for (int base = start; base < end; base += 128) {
        int i = base + t;
        if (i < end) {
            int sc = g_col[i];
            float wv = __expf(lrelu(g_esrc2[sc] + ed));
            ss += wv;
            wbuf[t] = wv;
            scol[t] = sc;
        }
        __syncthreads();
        int cnt = min(128, end - base);
        int j = 0;
        for (; j + 3 < cnt; j += 4) {
            int s0 = scol[j], s1 = scol[j + 1], s2 = scol[j + 2], s3 = scol[j + 3];
            float w0 = wbuf[j], w1 = wbuf[j + 1], w2 = wbuf[j + 2], w3 = wbuf[j + 3];
            float v0 = g_h3[(size_t)s0 * C2 + t];
            float v1 = g_h3[(size_t)s1 * C2 + t];
            float v2 = g_h3[(size_t)s2 * C2 + t];
            float v3 = g_h3[(size_t)s3 * C2 + t];
            acc = fmaf(w0, v0, acc);
            acc = fmaf(w1, v1, acc);
            acc = fmaf(w2, v2, acc);
            acc = fmaf(w3, v3, acc);
        }
        for (; j < cnt; j++)
            acc = fmaf(wbuf[j], g_h3[(size_t)scol[j] * C2 + t], acc);
        __syncthreads();
    }

#pragma unroll
    for (int off = 16; off; off >>= 1) ss += __shfl_xor_sync(0xffffffffu, ss, off);
    if (lane == 0) sred[w] = ss;
    __syncthreads();
    float s = sred[0] + sred[1] + sred[2] + sred[3];
    float inv = (s > 0.f) ? 1.f / s : 0.f;
    out[(size_t)n * C2 + t] = acc * inv + b2[t];
}

// ---------------- launch ----------------
extern "C" void kernel_launch(void* const* d_in, const int* in_sizes, int n_in,
                              void* d_out, int out_size) {
    const float* x    = (const float*)d_in[0];
    const int*   ei   = (const int*)d_in[1];
    const float* sent = (const float*)d_in[2];
    const float* W1   = (const float*)d_in[3];
    const float* a1s  = (const float*)d_in[4];
    const float* a1d  = (const float*)d_in[5];
    const float* b1   = (const float*)d_in[6];
    const float* W2   = (const float*)d_in[7];
    const float* a2s  = (const float*)d_in[8];
    const float* a2d  = (const float*)d_in[9];
    const float* b2   = (const float*)d_in[10];
    float* out = (float*)d_out;

    int N = in_sizes[0] / SED;   // 20000
    int E = in_sizes[1] / 2;     // 320000
    int nb = (N + 511) / 512;    // scan blocks (<=64)

    float *p_h1, *p_act1, *p_h3, *p_c1, *p_es1, *p_ed1, *p_es2, *p_ed2;
    int *p_cnt;
    cudaGetSymbolAddress((void**)&p_h1,   g_h1);
    cudaGetSymbolAddress((void**)&p_act1, g_act1);
    cudaGetSymbolAddress((void**)&p_h3,   g_h3);
    cudaGetSymbolAddress((void**)&p_c1,   g_c1);
    cudaGetSymbolAddress((void**)&p_es1,  g_esrc1);
    cudaGetSymbolAddress((void**)&p_ed1,  g_edst1);
    cudaGetSymbolAddress((void**)&p_es2,  g_esrc2);
    cudaGetSymbolAddress((void**)&p_ed2,  g_edst2);
    cudaGetSymbolAddress((void**)&p_cnt,  g_cnt);

    const int gsmem = GSMEM_FLOATS * 4;   // 82944 B
    cudaFuncSetAttribute(k_gemm_tf32, cudaFuncAttributeMaxDynamicSharedMemorySize, gsmem);

    // CSR build (dst-sorted)
    cudaMemsetAsync(p_cnt, 0, N * sizeof(int));
    k_count<<<(E + 255) / 256, 256>>>(ei, E);
    k_scan1<<<nb, 512>>>(N);
    k_scan2<<<1, 64>>>(nb);
    k_scan3<<<(N + 255) / 256, 256>>>(N);
    k_scatter<<<(E + 255) / 256, 256>>>(ei, E);

    // Layer 1: GEMM + fused e-dots
    k_constvec<<<2, 256>>>(sent, W1);
    k_gemm_tf32<<<dim3((N + 127) / 128, HC1 / 128), 256, gsmem>>>(
        x, W1, p_h1, p_c1, a1s, a1d, p_es1, p_ed1, 4, N, HC1, SED);
    k_agg1<<<N, 128>>>(b1);

    // Layer 2: GEMM + fused e-dots
    k_gemm_tf32<<<dim3((N + 127) / 128, C2 / 128), 256, gsmem>>>(
        p_act1, W2, p_h3, nullptr, a2s, a2d, p_es2, p_ed2, 1, N, C2, HC1);
    k_agg2<<<N, 128>>>(b2, out);
}

// round 9
// speedup vs baseline: 1.1807x; 1.1807x over previous
#include <cuda_runtime.h>
#include <stdint.h>
#include <math.h>

// Problem constants (fixed shapes for this problem)
#define MAXN 20000
#define MAXE 320000
#define SED  768
#define HC1  512      // 4 heads * 128
#define C1   128
#define H1   4
#define C2   128

// ---------------- scratch (no allocation allowed; bss device globals) ----------------
__device__ __align__(16) float g_h1[MAXN * HC1];     // layer1 pre-attention features
__device__ __align__(16) float g_act1[MAXN * HC1];   // layer1 output after elu
__device__ __align__(16) float g_h3[MAXN * C2];      // layer2 pre-attention features
__device__ __align__(16) float g_esrc1[MAXN * 4];
__device__ __align__(16) float g_edst1[MAXN * 4];
__device__ float g_esrc2[MAXN];
__device__ float g_edst2[MAXN];
__device__ __align__(16) float g_c1[HC1];            // sent @ W1[768:] constant vector
__device__ int g_cnt[MAXN];
__device__ int g_rowptr[MAXN + 1];
__device__ int g_cursor[MAXN];
__device__ int g_col[MAXE];
__device__ int g_bsum[64];
__device__ int g_boff[64];

__device__ __forceinline__ float lrelu(float x) { return x > 0.f ? x : 0.2f * x; }

__device__ __forceinline__ unsigned f2tf32(float f) {
    unsigned o;
    asm("cvt.rna.tf32.f32 %0, %1;" : "=r"(o) : "f"(f));
    return o;
}

// ---------------- CSR build ----------------
__global__ void k_count(const int* __restrict__ ei, int E) {
    int i = blockIdx.x * blockDim.x + threadIdx.x;
    if (i < E) atomicAdd(&g_cnt[ei[E + i]], 1);
}

__global__ void k_scan1(int N) {
    __shared__ int sm[512];
    int b = blockIdx.x, t = threadIdx.x, i = b * 512 + t;
    int v = (i < N) ? g_cnt[i] : 0;
    sm[t] = v;
    __syncthreads();
#pragma unroll
    for (int off = 1; off < 512; off <<= 1) {
        int u = (t >= off) ? sm[t - off] : 0;
        __syncthreads();
        sm[t] += u;
        __syncthreads();
    }
    if (i < N) g_rowptr[i + 1] = sm[t];
    if (t == 511) g_bsum[b] = sm[511];
}

__global__ void k_scan2(int nb) {
    __shared__ int sm[64];
    int t = threadIdx.x;
    int v = (t < nb) ? g_bsum[t] : 0;
    sm[t] = v;
    __syncthreads();
#pragma unroll
    for (int off = 1; off < 64; off <<= 1) {
        int u = (t >= off) ? sm[t - off] : 0;
        __syncthreads();
        sm[t] += u;
        __syncthreads();
    }
    if (t < nb) g_boff[t] = sm[t] - v;
}

__global__ void k_scan3(int N) {
    int i = blockIdx.x * blockDim.x + threadIdx.x;
    if (i < N) {
        int r = g_rowptr[i + 1] + g_boff[i >> 9];
        g_rowptr[i + 1] = r;
        g_cursor[i] = r - g_cnt[i];
    }
    if (i == 0) g_rowptr[0] = 0;
}

__global__ void k_scatter(const int* __restrict__ ei, int E) {
    int i = blockIdx.x * blockDim.x + threadIdx.x;
    if (i < E) {
        int dst = ei[E + i], src = ei[i];
        int pos = atomicAdd(&g_cursor[dst], 1);
        g_col[pos] = src;
    }
}

// ---------------- constant vector: c1 = sent @ W1[768:1536, :] ----------------
__global__ void k_constvec(const float* __restrict__ sent, const float* __restrict__ W1) {
    int j = blockIdx.x * blockDim.x + threadIdx.x;
    if (j < HC1) {
        float s = 0.f;
        for (int k = 0; k < SED; k++)
            s += sent[k] * W1[(size_t)(SED + k) * HC1 + j];
        g_c1[j] = s;
    }
}

// ---------------- TF32 tensor-core GEMM (double-buffered, register-staged, cvt.rna) ----
// C[M,N] = A[M,K] @ B[K,N] (+ addv[col]); fused per-row dots with a_src/a_dst over this
// CTA's 128-col block -> es_out[row*es_stride + blockIdx.y], ed_out likewise.
// N % 128 == 0, K % 16 == 0; M bounds-checked.
#define LDA 24
#define LDB 132
__global__ __launch_bounds__(256, 2)
void k_gemm_tf32(const float* __restrict__ A, const float* __restrict__ B,
                 float* __restrict__ C, const float* __restrict__ addv,
                 const float* __restrict__ asrc, const float* __restrict__ adst,
                 float* __restrict__ es_out, float* __restrict__ ed_out,
                 int es_stride, int M, int N, int K) {
    __shared__ float As[2][128 * LDA];
    __shared__ float Bs[2][16 * LDB];

    int tid = threadIdx.x;
    int lane = tid & 31, wid = tid >> 5;
    int g = lane >> 2, t = lane & 3;
    int wm = (wid >> 2) * 64, wn = (wid & 3) * 32;
    int m0 = blockIdx.x * 128, n0 = blockIdx.y * 128;

    int a_row = tid >> 1;
    int a_k   = (tid & 1) * 4;
    int b_kr  = tid >> 5;
    int b_n   = (tid & 31) * 4;

    bool a_ok = (m0 + a_row) < M;
    const float* Aptr = A + (size_t)(m0 + a_row) * K;
    const float* Bptr = B + (size_t)n0;

    float acc[4][4][4];
#pragma unroll
    for (int mi = 0; mi < 4; mi++)
#pragma unroll
        for (int ni = 0; ni < 4; ni++)
#pragma unroll
            for (int c = 0; c < 4; c++) acc[mi][ni][c] = 0.f;

    float4 ra0, ra1, rb0, rb1;
    const float4 fz = make_float4(0.f, 0.f, 0.f, 0.f);

    {
        int kb = 0;
        ra0 = a_ok ? *(const float4*)&Aptr[kb + a_k]     : fz;
        ra1 = a_ok ? *(const float4*)&Aptr[kb + a_k + 8] : fz;
        rb0 = *(const float4*)&Bptr[(size_t)(kb + b_kr) * N + b_n];
        rb1 = *(const float4*)&Bptr[(size_t)(kb + b_kr + 8) * N + b_n];
        float* as = &As[0][a_row * LDA + a_k];
        as[0] = __uint_as_float(f2tf32(ra0.x)); as[1] = __uint_as_float(f2tf32(ra0.y));
        as[2] = __uint_as_float(f2tf32(ra0.z)); as[3] = __uint_as_float(f2tf32(ra0.w));
        as[8] = __uint_as_float(f2tf32(ra1.x)); as[9] = __uint_as_float(f2tf32(ra1.y));
        as[10] = __uint_as_float(f2tf32(ra1.z)); as[11] = __uint_as_float(f2tf32(ra1.w));
        float* bs0 = &Bs[0][b_kr * LDB + b_n];
        float* bs1 = &Bs[0][(b_kr + 8) * LDB + b_n];
        bs0[0] = __uint_as_float(f2tf32(rb0.x)); bs0[1] = __uint_as_float(f2tf32(rb0.y));
        bs0[2] = __uint_as_float(f2tf32(rb0.z)); bs0[3] = __uint_as_float(f2tf32(rb0.w));
        bs1[0] = __uint_as_float(f2tf32(rb1.x)); bs1[1] = __uint_as_float(f2tf32(rb1.y));
        bs1[2] = __uint_as_float(f2tf32(rb1.z)); bs1[3] = __uint_as_float(f2tf32(rb1.w));
    }
    __syncthreads();

    int nk = K / 16;
    for (int kt = 0; kt < nk; kt++) {
        int cur = kt & 1;
        if (kt + 1 < nk) {
            int kb = (kt + 1) * 16;
            ra0 = a_ok ? *(const float4*)&Aptr[kb + a_k]     : fz;
            ra1 = a_ok ? *(const float4*)&Aptr[kb + a_k + 8] : fz;
            rb0 = *(const float4*)&Bptr[(size_t)(kb + b_kr) * N + b_n];
            rb1 = *(const float4*)&Bptr[(size_t)(kb + b_kr + 8) * N + b_n];
        }

        const float* as = As[cur];
        const float* bs = Bs[cur];
#pragma unroll
        for (int ks = 0; ks < 2; ks++) {
            int kb = ks * 8;
            float2 af[4][2];
#pragma unroll
            for (int mi = 0; mi < 4; mi++) {
                int r = wm + mi * 16 + g;
                af[mi][0] = *(const float2*)&as[r * LDA + kb + 2 * t];
                af[mi][1] = *(const float2*)&as[(r + 8) * LDA + kb + 2 * t];
            }
#pragma unroll
            for (int ni = 0; ni < 4; ni++) {
                int cidx = wn + ni * 8 + g;
                unsigned b0 = __float_as_uint(bs[(kb + 2 * t) * LDB + cidx]);
                unsigned b1 = __float_as_uint(bs[(kb + 2 * t + 1) * LDB + cidx]);
#pragma unroll
                for (int mi = 0; mi < 4; mi++) {
                    unsigned a0 = __float_as_uint(af[mi][0].x);
                    unsigned a1 = __float_as_uint(af[mi][1].x);
                    unsigned a2 = __float_as_uint(af[mi][0].y);
                    unsigned a3 = __float_as_uint(af[mi][1].y);
                    asm volatile(
                        "mma.sync.aligned.m16n8k8.row.col.f32.tf32.tf32.f32 "
                        "{%0,%1,%2,%3}, {%4,%5,%6,%7}, {%8,%9}, {%0,%1,%2,%3};"
                        : "+f"(acc[mi][ni][0]), "+f"(acc[mi][ni][1]),
                          "+f"(acc[mi][ni][2]), "+f"(acc[mi][ni][3])
                        : "r"(a0), "r"(a1), "r"(a2), "r"(a3), "r"(b0), "r"(b1));
                }
            }
        }

        if (kt + 1 < nk) {
            int nxt = (kt + 1) & 1;
            float* asw = &As[nxt][a_row * LDA + a_k];
            asw[0] = __uint_as_float(f2tf32(ra0.x)); asw[1] = __uint_as_float(f2tf32(ra0.y));
            asw[2] = __uint_as_float(f2tf32(ra0.z)); asw[3] = __uint_as_float(f2tf32(ra0.w));
            asw[8] = __uint_as_float(f2tf32(ra1.x)); asw[9] = __uint_as_float(f2tf32(ra1.y));
            asw[10] = __uint_as_float(f2tf32(ra1.z)); asw[11] = __uint_as_float(f2tf32(ra1.w));
            float* bs0 = &Bs[nxt][b_kr * LDB + b_n];
            float* bs1 = &Bs[nxt][(b_kr + 8) * LDB + b_n];
            bs0[0] = __uint_as_float(f2tf32(rb0.x)); bs0[1] = __uint_as_float(f2tf32(rb0.y));
            bs0[2] = __uint_as_float(f2tf32(rb0.z)); bs0[3] = __uint_as_float(f2tf32(rb0.w));
            bs1[0] = __uint_as_float(f2tf32(rb1.x)); bs1[1] = __uint_as_float(f2tf32(rb1.y));
            bs1[2] = __uint_as_float(f2tf32(rb1.z)); bs1[3] = __uint_as_float(f2tf32(rb1.w));
            __syncthreads();
        }
    }

    // attention vectors for this CTA's cols
    float a_s[8], a_d[8];
#pragma unroll
    for (int ni = 0; ni < 4; ni++)
#pragma unroll
        for (int j = 0; j < 2; j++) {
            int c = n0 + wn + ni * 8 + 2 * t + j;
            a_s[ni * 2 + j] = asrc[c];
            a_d[ni * 2 + j] = adst[c];
        }

    __syncthreads();   // all warps done reading As/Bs before smem reuse below

    // epilogue: store C (+addv), accumulate per-row dots
    float* sds = &As[0][0];          // [128][4]
    float* sdd = &As[0][512];        // [128][4]
#pragma unroll
    for (int mi = 0; mi < 4; mi++) {
#pragma unroll
        for (int half = 0; half < 2; half++) {
            int rl = wm + mi * 16 + g + half * 8;
            int r = m0 + rl;
            float ps = 0.f, pd = 0.f;
#pragma unroll
            for (int ni = 0; ni < 4; ni++) {
                int c = n0 + wn + ni * 8 + 2 * t;
                float2 v;
                v.x = acc[mi][ni][half * 2 + 0];
                v.y = acc[mi][ni][half * 2 + 1];
                if (addv) { v.x += addv[c]; v.y += addv[c + 1]; }
                if (r < M) *(float2*)&C[(size_t)r * N + c] = v;
                ps = fmaf(v.x, a_s[ni * 2], ps);
                ps = fmaf(v.y, a_s[ni * 2 + 1], ps);
                pd = fmaf(v.x, a_d[ni * 2], pd);
                pd = fmaf(v.y, a_d[ni * 2 + 1], pd);
            }
            // reduce across the 4 t-lanes sharing this row
            ps += __shfl_xor_sync(0xffffffffu, ps, 1);
            ps += __shfl_xor_sync(0xffffffffu, ps, 2);
            pd += __shfl_xor_sync(0xffffffffu, pd, 1);
            pd += __shfl_xor_sync(0xffffffffu, pd, 2);
            if (t == 0) { sds[rl * 4 + (wid & 3)] = ps; sdd[rl * 4 + (wid & 3)] = pd; }
        }
    }
    __syncthreads();
    if (tid < 128) {
        int r = m0 + tid;
        if (r < M) {
            float s = sds[tid * 4] + sds[tid * 4 + 1] + sds[tid * 4 + 2] + sds[tid * 4 + 3];
            float d = sdd[tid * 4] + sdd[tid * 4 + 1] + sdd[tid * 4 + 2] + sdd[tid * 4 + 3];
            es_out[(size_t)r * es_stride + blockIdx.y] = s;
            ed_out[(size_t)r * es_stride + blockIdx.y] = d;
        }
    }
}

// ---------------- layer 1 aggregation: single-sweep normalization ----------------
__global__ void k_agg1(const float* __restrict__ b1) {
    int n = blockIdx.x;
    int t = threadIdx.x, lane = t & 31, w = t >> 5;
    int start = g_rowptr[n], end = g_rowptr[n + 1];
    float4 edv = *(const float4*)&g_edst1[n * 4];

    __shared__ float4 wbuf[128];
    __shared__ int scol[128];
    __shared__ float sred[4][4];

    float acc[4] = {0.f, 0.f, 0.f, 0.f};
    float ss[4]  = {0.f, 0.f, 0.f, 0.f};

    for (int base = start; base < end; base += 128) {
        int i = base + t;
        if (i < end) {
            int sc = g_col[i];
            float4 es = *(const float4*)&g_esrc1[sc * 4];
            float4 wv;
            wv.x = __expf(lrelu(es.x + edv.x));
            wv.y = __expf(lrelu(es.y + edv.y));
            wv.z = __expf(lrelu(es.z + edv.z));
            wv.w = __expf(lrelu(es.w + edv.w));
            ss[0] += wv.x; ss[1] += wv.y; ss[2] += wv.z; ss[3] += wv.w;
            wbuf[t] = wv;
            scol[t] = sc;
        }
        __syncthreads();
        int cnt = min(128, end - base);
        int j = 0;
        for (; j + 1 < cnt; j += 2) {
            int s0 = scol[j], s1 = scol[j + 1];
            float4 w0 = wbuf[j], w1 = wbuf[j + 1];
            const float* p0 = &g_h1[(size_t)s0 * HC1];
            const float* p1 = &g_h1[(size_t)s1 * HC1];
            float v00 = p0[t], v01 = p0[128 + t], v02 = p0[256 + t], v03 = p0[384 + t];
            float v10 = p1[t], v11 = p1[128 + t], v12 = p1[256 + t], v13 = p1[384 + t];
            acc[0] = fmaf(w0.x, v00, acc[0]);
            acc[1] = fmaf(w0.y, v01, acc[1]);
            acc[2] = fmaf(w0.z, v02, acc[2]);
            acc[3] = fmaf(w0.w, v03, acc[3]);
            acc[0] = fmaf(w1.x, v10, acc[0]);
            acc[1] = fmaf(w1.y, v11, acc[1]);
            acc[2] = fmaf(w1.z, v12, acc[2]);
            acc[3] = fmaf(w1.w, v13, acc[3]);
        }
        if (j < cnt) {
            int s0 = scol[j];
            float4 w0 = wbuf[j];
            const float* p0 = &g_h1[(size_t)s0 * HC1];
            acc[0] = fmaf(w0.x, p0[t],       acc[0]);
            acc[1] = fmaf(w0.y, p0[128 + t], acc[1]);
            acc[2] = fmaf(w0.z, p0[256 + t], acc[2]);
            acc[3] = fmaf(w0.w, p0[384 + t], acc[3]);
        }
        __syncthreads();
    }

#pragma unroll
    for (int h = 0; h < 4; h++)
#pragma unroll
        for (int off = 16; off; off >>= 1)
            ss[h] += __shfl_xor_sync(0xffffffffu, ss[h], off);
    if (lane == 0) { sred[0][w] = ss[0]; sred[1][w] = ss[1]; sred[2][w] = ss[2]; sred[3][w] = ss[3]; }
    __syncthreads();

    float* orow = &g_act1[(size_t)n * HC1];
#pragma unroll
    for (int h = 0; h < 4; h++) {
        float s = sred[h][0] + sred[h][1] + sred[h][2] + sred[h][3];
        float inv = (s > 0.f) ? 1.f / s : 0.f;   // deg-0 node -> out = bias
        float v = acc[h] * inv + b1[h * C1 + t];
        orow[h * C1 + t] = v > 0.f ? v : expm1f(v);
    }
}

// ---------------- layer 2 aggregation -> final output ----------------
__global__ void k_agg2(const float* __restrict__ b2, float* __restrict__ out) {
    int n = blockIdx.x;
    int t = threadIdx.x, lane = t & 31, w = t >> 5;
    int start = g_rowptr[n], end = g_rowptr[n + 1];
    float ed = g_edst2[n];

    __shared__ float wbuf[128];
    __shared__ int scol[128];
    __shared__ float sred[4];

    float acc = 0.f, ss = 0.f;

    for (int base = start; base < end; base += 128) {
        int i = base + t;
        if (i < end) {
            int sc = g_col[i];
            float wv = __expf(lrelu(g_esrc2[sc] + ed));
            ss += wv;
            wbuf[t] = wv;
            scol[t] = sc;
        }
        __syncthreads();
        int cnt = min(128, end - base);
        int j = 0;
        for (; j + 3 < cnt; j += 4) {
            int s0 = scol[j], s1 = scol[j + 1], s2 = scol[j + 2], s3 = scol[j + 3];
            float w0 = wbuf[j], w1 = wbuf[j + 1], w2 = wbuf[j + 2], w3 = wbuf[j + 3];
            float v0 = g_h3[(size_t)s0 * C2 + t];
            float v1 = g_h3[(size_t)s1 * C2 + t];
            float v2 = g_h3[(size_t)s2 * C2 + t];
            float v3 = g_h3[(size_t)s3 * C2 + t];
            acc = fmaf(w0, v0, acc);
            acc = fmaf(w1, v1, acc);
            acc = fmaf(w2, v2, acc);
            acc = fmaf(w3, v3, acc);
        }
        for (; j < cnt; j++)
            acc = fmaf(wbuf[j], g_h3[(size_t)scol[j] * C2 + t], acc);
        __syncthreads();
    }

#pragma unroll
    for (int off = 16; off; off >>= 1) ss += __shfl_xor_sync(0xffffffffu, ss, off);
    if (lane == 0) sred[w] = ss;
    __syncthreads();
    float s = sred[0] + sred[1] + sred[2] + sred[3];
    float inv = (s > 0.f) ? 1.f / s : 0.f;
    out[(size_t)n * C2 + t] = acc * inv + b2[t];
}

// ---------------- launch ----------------
extern "C" void kernel_launch(void* const* d_in, const int* in_sizes, int n_in,
                              void* d_out, int out_size) {
    const float* x    = (const float*)d_in[0];
    const int*   ei   = (const int*)d_in[1];
    const float* sent = (const float*)d_in[2];
    const float* W1   = (const float*)d_in[3];
    const float* a1s  = (const float*)d_in[4];
    const float* a1d  = (const float*)d_in[5];
    const float* b1   = (const float*)d_in[6];
    const float* W2   = (const float*)d_in[7];
    const float* a2s  = (const float*)d_in[8];
    const float* a2d  = (const float*)d_in[9];
    const float* b2   = (const float*)d_in[10];
    float* out = (float*)d_out;

    int N = in_sizes[0] / SED;   // 20000
    int E = in_sizes[1] / 2;     // 320000
    int nb = (N + 511) / 512;    // scan blocks (<=64)

    float *p_h1, *p_act1, *p_h3, *p_c1, *p_es1, *p_ed1, *p_es2, *p_ed2;
    int *p_cnt;
    cudaGetSymbolAddress((void**)&p_h1,   g_h1);
    cudaGetSymbolAddress((void**)&p_act1, g_act1);
    cudaGetSymbolAddress((void**)&p_h3,   g_h3);
    cudaGetSymbolAddress((void**)&p_c1,   g_c1);
    cudaGetSymbolAddress((void**)&p_es1,  g_esrc1);
    cudaGetSymbolAddress((void**)&p_ed1,  g_edst1);
    cudaGetSymbolAddress((void**)&p_es2,  g_esrc2);
    cudaGetSymbolAddress((void**)&p_ed2,  g_edst2);
    cudaGetSymbolAddress((void**)&p_cnt,  g_cnt);

    // CSR build (dst-sorted)
    cudaMemsetAsync(p_cnt, 0, N * sizeof(int));
    k_count<<<(E + 255) / 256, 256>>>(ei, E);
    k_scan1<<<nb, 512>>>(N);
    k_scan2<<<1, 64>>>(nb);
    k_scan3<<<(N + 255) / 256, 256>>>(N);
    k_scatter<<<(E + 255) / 256, 256>>>(ei, E);

    // Layer 1: GEMM + fused e-dots
    k_constvec<<<2, 256>>>(sent, W1);
    k_gemm_tf32<<<dim3((N + 127) / 128, HC1 / 128), 256>>>(
        x, W1, p_h1, p_c1, a1s, a1d, p_es1, p_ed1, 4, N, HC1, SED);
    k_agg1<<<N, 128>>>(b1);

    // Layer 2: GEMM + fused e-dots
    k_gemm_tf32<<<dim3((N + 127) / 128, C2 / 128), 256>>>(
        p_act1, W2, p_h3, nullptr, a2s, a2d, p_es2, p_ed2, 1, N, C2, HC1);
    k_agg2<<<N, 128>>>(b2, out);
}